// round 1
// baseline (speedup 1.0000x reference)
#include <cuda_runtime.h>
#include <math.h>

#define NB   8
#define NC   256
#define NH   128
#define NW   128
#define NHW  16384
#define NMID 64
#define NANG 4
#define NPT  512   // number of 32-pixel tiles per image plane

// ---------------- scratch (static __device__, no allocations) ----------------
__device__ float g_xnhwc[(size_t)NB * NHW * NC];   // 134 MB  x in NHWC
__device__ float g_fnhwc[(size_t)NB * NHW * NC];   // 134 MB  fused accumulator NHWC
__device__ float g_trig[2 * NANG];                 // cos,sin per angle
__device__ float g_A[NANG * NHW];                  // accumulated fwd bilinear weights (×1/HW)
__device__ float g_mpart[(size_t)NANG * NB * NC * NPT]; // mean partials
__device__ float g_mean[NANG * NB * NC];
__device__ float g_ca[NANG * NB * NC];
__device__ float g_avg[(size_t)NANG * NB * NHW];
__device__ float g_maxm[(size_t)NANG * NB * NHW];
__device__ float g_sa[(size_t)NANG * NB * NHW];

// ---------------- helpers ----------------
__device__ __forceinline__ float ncoord(int j) { return -1.0f + (float)j * (2.0f / 127.0f); }
__device__ __forceinline__ float sigm(float v) { return 1.0f / (1.0f + expf(-v)); }

__device__ __forceinline__ void fma4(float4& a, float w, const float4 v) {
    a.x = fmaf(w, v.x, a.x); a.y = fmaf(w, v.y, a.y);
    a.z = fmaf(w, v.z, a.z); a.w = fmaf(w, v.w, a.w);
}
__device__ __forceinline__ void fma44(float4& a, const float4 w, const float4 v) {
    a.x = fmaf(w.x, v.x, a.x); a.y = fmaf(w.y, v.y, a.y);
    a.z = fmaf(w.z, v.z, a.z); a.w = fmaf(w.w, v.w, a.w);
}

// Bilinear gather of one NHWC pixel-row neighborhood into two float4 channel
// chunks (lane covers c = lane*4..lane*4+3 and 128+lane*4..). Warp-uniform
// control flow (coords identical across lanes).
__device__ __forceinline__ void gather_xr(int b, float fix, float fiy, int lane,
                                          float4& xr0, float4& xr1) {
    float fx0 = floorf(fix), fy0 = floorf(fiy);
    float wx1 = fix - fx0, wx0 = 1.0f - wx1;
    float wy1 = fiy - fy0, wy0 = 1.0f - wy1;
    float cx[4] = {fx0, fx0 + 1.0f, fx0,        fx0 + 1.0f};
    float cy[4] = {fy0, fy0,        fy0 + 1.0f, fy0 + 1.0f};
    float cw[4] = {wx0 * wy0, wx1 * wy0, wx0 * wy1, wx1 * wy1};
    xr0 = make_float4(0.f, 0.f, 0.f, 0.f);
    xr1 = make_float4(0.f, 0.f, 0.f, 0.f);
#pragma unroll
    for (int k = 0; k < 4; k++) {
        float fx = cx[k], fy = cy[k], wv = cw[k];
        if (fx >= 0.f && fx <= 127.f && fy >= 0.f && fy <= 127.f && wv != 0.f) {
            const float4* row = (const float4*)(g_xnhwc +
                ((size_t)b * NHW + (int)fy * NW + (int)fx) * NC);
            fma4(xr0, wv, row[lane]);
            fma4(xr1, wv, row[lane + 32]);
        }
    }
}

// ---------------- kernels ----------------

__global__ void k_trig(const float* __restrict__ angles) {
    int i = threadIdx.x;
    if (i < NANG) {
        float a = angles[i];
        g_trig[2 * i]     = cosf(a);
        g_trig[2 * i + 1] = sinf(a);
    }
}

// A_a[src] = (1/HW) * sum over output pixels p of the bilinear tent weight that
// p's forward sample puts on integer pixel src. Deterministic gather: only
// pixels p within sqrt(2) of R^{-1}(src) (rotation about 63.5) can contribute;
// scan a 5x5 window around the rounded back-rotated position.
__global__ void k_Amap() {
    int id = blockIdx.x * 256 + threadIdx.x;
    if (id >= NANG * NHW) return;
    int a = id / NHW, src = id % NHW;
    int sy = src >> 7, sx = src & 127;
    float c_ = g_trig[2 * a], s_ = g_trig[2 * a + 1];
    float dx = (float)sx - 63.5f, dy = (float)sy - 63.5f;
    float pxf = c_ * dx + s_ * dy + 63.5f;   // R_{-theta}(src)
    float pyf = -s_ * dx + c_ * dy + 63.5f;
    int px0 = (int)floorf(pxf + 0.5f) - 2;
    int py0 = (int)floorf(pyf + 0.5f) - 2;
    float acc = 0.f;
    for (int py = py0; py < py0 + 5; py++) {
        for (int px = px0; px < px0 + 5; px++) {
            if ((unsigned)px < 128u && (unsigned)py < 128u) {
                float X = ncoord(px), Y = ncoord(py);
                float gx = c_ * X - s_ * Y, gy = s_ * X + c_ * Y;
                float ix = (gx + 1.0f) * 63.5f, iy = (gy + 1.0f) * 63.5f;
                float tx = 1.0f - fabsf(ix - (float)sx);
                float ty = 1.0f - fabsf(iy - (float)sy);
                if (tx > 0.f && ty > 0.f) acc += tx * ty;
            }
        }
    }
    g_A[id] = acc * (1.0f / (float)NHW);
}

// NCHW -> NHWC transpose fused with per-angle weighted-mean partials.
// Block = 32x32 tile (pixels x channels); warp-level reductions are
// fixed-order -> deterministic.
__global__ void k_transpose_mean(const float* __restrict__ x) {
    __shared__ float s[32][33];
    int b = blockIdx.z, c0 = blockIdx.y * 32, p0 = blockIdx.x * 32;
    int tx = threadIdx.x, ty = threadIdx.y;
    float val = x[((size_t)(b * NC + c0 + ty)) * NHW + p0 + tx];
    s[ty][tx] = val;
#pragma unroll
    for (int a = 0; a < NANG; a++) {
        float r = val * g_A[a * NHW + p0 + tx];
#pragma unroll
        for (int o = 16; o; o >>= 1) r += __shfl_xor_sync(0xffffffffu, r, o);
        if (tx == 0)
            g_mpart[((size_t)((a * NB + b) * NC + c0 + ty)) * NPT + blockIdx.x] = r;
    }
    __syncthreads();
    g_xnhwc[((size_t)b * NHW + p0 + ty) * NC + c0 + tx] = s[tx][ty];
}

__global__ void k_mean_reduce() {
    int wid = blockIdx.x * 8 + (threadIdx.x >> 5);
    int lane = threadIdx.x & 31;
    const float* src = g_mpart + (size_t)wid * NPT;
    float s = 0.f;
    for (int i = lane; i < NPT; i += 32) s += src[i];
#pragma unroll
    for (int o = 16; o; o >>= 1) s += __shfl_xor_sync(0xffffffffu, s, o);
    if (lane == 0) g_mean[wid] = s;
}

// Channel attention: mean -> w1 -> BN -> relu -> w2 -> sigmoid. One block per (angle,batch).
__global__ void k_chatt(const float* __restrict__ w1, const float* __restrict__ bng,
                        const float* __restrict__ bnb, const float* __restrict__ bnm,
                        const float* __restrict__ bnv, const float* __restrict__ w2) {
    __shared__ float sm[NC];
    __shared__ float sh[NMID];
    int ab = blockIdx.x;           // a*NB + b
    int tid = threadIdx.x;
    sm[tid] = g_mean[ab * NC + tid];
    __syncthreads();
    if (tid < NMID) {
        float hv = 0.f;
        const float* w1r = w1 + tid * NC;
        for (int c = 0; c < NC; c++) hv = fmaf(sm[c], w1r[c], hv);
        hv = (hv - bnm[tid]) * rsqrtf(bnv[tid] + 1e-5f) * bng[tid] + bnb[tid];
        sh[tid] = fmaxf(hv, 0.f);
    }
    __syncthreads();
    float cv = 0.f;
    const float* w2r = w2 + tid * NMID;
    for (int j = 0; j < NMID; j++) cv = fmaf(sh[j], w2r[j], cv);
    g_ca[ab * NC + tid] = sigm(cv);
}

// Per (angle,batch,pixel): channel-attended rotated value stats (avg, max over C).
// One warp per pixel; channel dim via 2 float4 per lane (fully coalesced NHWC rows).
__global__ void k_avgmax() {
    int w = blockIdx.x * 8 + (threadIdx.x >> 5);
    int lane = threadIdx.x & 31;
    int a = w >> 17;               // B*HW = 2^17
    int b = (w >> 14) & 7;
    int p = w & (NHW - 1);
    float c_ = g_trig[2 * a], s_ = g_trig[2 * a + 1];
    float X = ncoord(p & 127), Y = ncoord(p >> 7);
    float gx = c_ * X - s_ * Y, gy = s_ * X + c_ * Y;
    float4 xr0, xr1;
    gather_xr(b, (gx + 1.0f) * 63.5f, (gy + 1.0f) * 63.5f, lane, xr0, xr1);
    const float4* car = (const float4*)(g_ca + (size_t)(a * NB + b) * NC);
    float4 ca0 = car[lane], ca1 = car[lane + 32];
    float v0 = ca0.x * xr0.x, v1 = ca0.y * xr0.y, v2 = ca0.z * xr0.z, v3 = ca0.w * xr0.w;
    float v4 = ca1.x * xr1.x, v5 = ca1.y * xr1.y, v6 = ca1.z * xr1.z, v7 = ca1.w * xr1.w;
    float sum = ((v0 + v1) + (v2 + v3)) + ((v4 + v5) + (v6 + v7));
    float mx = fmaxf(fmaxf(fmaxf(v0, v1), fmaxf(v2, v3)),
                     fmaxf(fmaxf(v4, v5), fmaxf(v6, v7)));
#pragma unroll
    for (int o = 16; o; o >>= 1) {
        sum += __shfl_xor_sync(0xffffffffu, sum, o);
        mx = fmaxf(mx, __shfl_xor_sync(0xffffffffu, mx, o));
    }
    if (lane == 0) {
        g_avg[w] = sum * (1.0f / (float)NC);
        g_maxm[w] = mx;
    }
}

// 7x7 conv over (avg,max) with pad 3, then sigmoid -> sa.
__global__ void k_conv(const float* __restrict__ wsp) {
    __shared__ float sw[98];
    int tid = threadIdx.x;
    if (tid < 98) sw[tid] = wsp[tid];
    __syncthreads();
    int id = blockIdx.x * 256 + tid;
    int ab = id >> 14;             // (a*NB+b); 256 | NHW so block shares ab
    int p = id & (NHW - 1);
    int py = p >> 7, px = p & 127;
    const float* av = g_avg + (size_t)ab * NHW;
    const float* mxp = g_maxm + (size_t)ab * NHW;
    float acc = 0.f;
#pragma unroll
    for (int ky = 0; ky < 7; ky++) {
        int yy = py + ky - 3;
        if ((unsigned)yy < 128u) {
#pragma unroll
            for (int kx = 0; kx < 7; kx++) {
                int xx = px + kx - 3;
                if ((unsigned)xx < 128u) {
                    int q = yy * NW + xx;
                    acc = fmaf(sw[ky * 7 + kx], av[q], acc);
                    acc = fmaf(sw[49 + ky * 7 + kx], mxp[q], acc);
                }
            }
        }
    }
    g_sa[id] = sigm(acc);
}

// Fully fused: for each output pixel q, sum over angles of the inverse-rotation
// bilinear gather of fatt = sa * ca * xr, where xr is itself a forward bilinear
// gather of x. Composition is near-identity -> all 16 gathers land within ~2px
// of q (L1-resident). One warp per pixel, NHWC float4 lanes. Writes NHWC.
__global__ void k_fused() {
    int w = blockIdx.x * 8 + (threadIdx.x >> 5);
    int lane = threadIdx.x & 31;
    int b = w >> 14;
    int q = w & (NHW - 1);
    float X = ncoord(q & 127), Y = ncoord(q >> 7);
    float4 acc0 = make_float4(0.f, 0.f, 0.f, 0.f), acc1 = acc0;
#pragma unroll
    for (int a = 0; a < NANG; a++) {
        float c_ = g_trig[2 * a], s_ = g_trig[2 * a + 1];
        // inverse grid: _rot_grid(c, -s)
        float gx = c_ * X + s_ * Y, gy = -s_ * X + c_ * Y;
        float ixv = (gx + 1.0f) * 63.5f, iyv = (gy + 1.0f) * 63.5f;
        float x0 = floorf(ixv), y0 = floorf(iyv);
        float wx1 = ixv - x0, wx0 = 1.0f - wx1;
        float wy1 = iyv - y0, wy0 = 1.0f - wy1;
        float cx[4] = {x0, x0 + 1.0f, x0,        x0 + 1.0f};
        float cy[4] = {y0, y0,        y0 + 1.0f, y0 + 1.0f};
        float cw[4] = {wx0 * wy0, wx1 * wy0, wx0 * wy1, wx1 * wy1};
        float4 t0 = make_float4(0.f, 0.f, 0.f, 0.f), t1 = t0;
#pragma unroll
        for (int k = 0; k < 4; k++) {
            float fx = cx[k], fy = cy[k], wi = cw[k];
            if (fx >= 0.f && fx <= 127.f && fy >= 0.f && fy <= 127.f && wi != 0.f) {
                int ppx = (int)fx, ppy = (int)fy;
                int p = ppy * NW + ppx;
                float sa = g_sa[(size_t)(a * NB + b) * NHW + p];
                float Xp = ncoord(ppx), Yp = ncoord(ppy);
                float fgx = c_ * Xp - s_ * Yp, fgy = s_ * Xp + c_ * Yp;
                float4 xr0, xr1;
                gather_xr(b, (fgx + 1.0f) * 63.5f, (fgy + 1.0f) * 63.5f, lane, xr0, xr1);
                float ws = wi * sa;
                fma4(t0, ws, xr0);
                fma4(t1, ws, xr1);
            }
        }
        const float4* car = (const float4*)(g_ca + (size_t)(a * NB + b) * NC);
        fma44(acc0, car[lane], t0);
        fma44(acc1, car[lane + 32], t1);
    }
    float4* o = (float4*)(g_fnhwc + ((size_t)b * NHW + q) * NC);
    o[lane] = acc0;
    o[lane + 32] = acc1;
}

// NHWC -> NCHW with division by n_ang.
__global__ void k_outT(float* __restrict__ out) {
    __shared__ float s[32][33];
    int b = blockIdx.z, c0 = blockIdx.y * 32, p0 = blockIdx.x * 32;
    int tx = threadIdx.x, ty = threadIdx.y;
    s[ty][tx] = g_fnhwc[((size_t)b * NHW + p0 + ty) * NC + c0 + tx];
    __syncthreads();
    out[((size_t)(b * NC + c0 + ty)) * NHW + p0 + tx] = s[tx][ty] * 0.25f;
}

// ---------------- launch ----------------
extern "C" void kernel_launch(void* const* d_in, const int* in_sizes, int n_in,
                              void* d_out, int out_size) {
    const float* x      = (const float*)d_in[0];
    const float* angles = (const float*)d_in[1];
    const float* w1     = (const float*)d_in[2];
    const float* bng    = (const float*)d_in[3];
    const float* bnb    = (const float*)d_in[4];
    const float* bnm    = (const float*)d_in[5];
    const float* bnv    = (const float*)d_in[6];
    const float* w2     = (const float*)d_in[7];
    const float* wsp    = (const float*)d_in[8];
    float* out = (float*)d_out;

    dim3 tb(32, 32);
    k_trig<<<1, 32>>>(angles);
    k_Amap<<<(NANG * NHW) / 256, 256>>>();
    k_transpose_mean<<<dim3(NPT, NC / 32, NB), tb>>>(x);
    k_mean_reduce<<<(NANG * NB * NC) / 8, 256>>>();
    k_chatt<<<NANG * NB, 256>>>(w1, bng, bnb, bnm, bnv, w2);
    k_avgmax<<<(NANG * NB * NHW) / 8, 256>>>();
    k_conv<<<(NANG * NB * NHW) / 256, 256>>>(wsp);
    k_fused<<<(NB * NHW) / 8, 256>>>();
    k_outT<<<dim3(NPT, NC / 32, NB), tb>>>(out);
}

// round 4
// speedup vs baseline: 1.0545x; 1.0545x over previous
#include <cuda_runtime.h>
#include <math.h>

#define NB   8
#define NC   256
#define NH   128
#define NW   128
#define NHW  16384
#define NMID 64
#define NANG 4
#define NPT  512   // number of 32-pixel tiles per image plane
#define WEPS 1e-5f

// ---------------- scratch (static __device__, no allocations) ----------------
__device__ float g_xnhwc[(size_t)NB * NHW * NC];   // 134 MB  x in NHWC
__device__ float g_trig[2 * NANG];                 // cos,sin per angle
__device__ float g_A[NANG * NHW];                  // accumulated fwd bilinear weights (x 1/HW)
__device__ float g_mpart[(size_t)NANG * NB * NC * NPT]; // mean partials
__device__ float g_mean[NANG * NB * NC];
__device__ float g_ca[NANG * NB * NC];
__device__ float g_avg[(size_t)NANG * NB * NHW];
__device__ float g_maxm[(size_t)NANG * NB * NHW];
__device__ float g_sa[(size_t)NANG * NB * NHW];

// ---------------- helpers ----------------
__device__ __forceinline__ float ncoord(int j) { return -1.0f + (float)j * (2.0f / 127.0f); }
__device__ __forceinline__ float sigm(float v) { return 1.0f / (1.0f + expf(-v)); }

__device__ __forceinline__ void fma4(float4& a, float w, const float4 v) {
    a.x = fmaf(w, v.x, a.x); a.y = fmaf(w, v.y, a.y);
    a.z = fmaf(w, v.z, a.z); a.w = fmaf(w, v.w, a.w);
}
__device__ __forceinline__ void fma44(float4& a, const float4 w, const float4 v) {
    a.x = fmaf(w.x, v.x, a.x); a.y = fmaf(w.y, v.y, a.y);
    a.z = fmaf(w.z, v.z, a.z); a.w = fmaf(w.w, v.w, a.w);
}

// Bilinear gather of one NHWC pixel-row neighborhood into two float4 channel
// chunks. Warp-uniform control flow; weights below WEPS skipped (makes the
// axis-aligned angles 1-corner instead of 4).
__device__ __forceinline__ void gather_xr(int b, float fix, float fiy, int lane,
                                          float4& xr0, float4& xr1) {
    float fx0 = floorf(fix), fy0 = floorf(fiy);
    float wx1 = fix - fx0, wx0 = 1.0f - wx1;
    float wy1 = fiy - fy0, wy0 = 1.0f - wy1;
    float cx[4] = {fx0, fx0 + 1.0f, fx0,        fx0 + 1.0f};
    float cy[4] = {fy0, fy0,        fy0 + 1.0f, fy0 + 1.0f};
    float cw[4] = {wx0 * wy0, wx1 * wy0, wx0 * wy1, wx1 * wy1};
    xr0 = make_float4(0.f, 0.f, 0.f, 0.f);
    xr1 = make_float4(0.f, 0.f, 0.f, 0.f);
#pragma unroll
    for (int k = 0; k < 4; k++) {
        float fx = cx[k], fy = cy[k], wv = cw[k];
        if (fx >= 0.f && fx <= 127.f && fy >= 0.f && fy <= 127.f && wv > WEPS) {
            const float4* row = (const float4*)(g_xnhwc +
                ((size_t)b * NHW + (int)fy * NW + (int)fx) * NC);
            fma4(xr0, wv, row[lane]);
            fma4(xr1, wv, row[lane + 32]);
        }
    }
}

// ---------------- kernels ----------------

__global__ void k_trig(const float* __restrict__ angles) {
    int i = threadIdx.x;
    if (i < NANG) {
        float a = angles[i];
        g_trig[2 * i]     = cosf(a);
        g_trig[2 * i + 1] = sinf(a);
    }
}

// A_a[src] = (1/HW) * sum over output pixels p of the bilinear tent weight that
// p's forward sample puts on integer pixel src. Deterministic gather over a 5x5
// window around the back-rotated position.
__global__ void k_Amap() {
    int id = blockIdx.x * 256 + threadIdx.x;
    if (id >= NANG * NHW) return;
    int a = id / NHW, src = id % NHW;
    int sy = src >> 7, sx = src & 127;
    float c_ = g_trig[2 * a], s_ = g_trig[2 * a + 1];
    float dx = (float)sx - 63.5f, dy = (float)sy - 63.5f;
    float pxf = c_ * dx + s_ * dy + 63.5f;
    float pyf = -s_ * dx + c_ * dy + 63.5f;
    int px0 = (int)floorf(pxf + 0.5f) - 2;
    int py0 = (int)floorf(pyf + 0.5f) - 2;
    float acc = 0.f;
    for (int py = py0; py < py0 + 5; py++) {
        for (int px = px0; px < px0 + 5; px++) {
            if ((unsigned)px < 128u && (unsigned)py < 128u) {
                float X = ncoord(px), Y = ncoord(py);
                float gx = c_ * X - s_ * Y, gy = s_ * X + c_ * Y;
                float ix = (gx + 1.0f) * 63.5f, iy = (gy + 1.0f) * 63.5f;
                float tx = 1.0f - fabsf(ix - (float)sx);
                float ty = 1.0f - fabsf(iy - (float)sy);
                if (tx > 0.f && ty > 0.f) acc += tx * ty;
            }
        }
    }
    g_A[id] = acc * (1.0f / (float)NHW);
}

// NCHW -> NHWC transpose fused with per-angle weighted-mean partials.
__global__ void k_transpose_mean(const float* __restrict__ x) {
    __shared__ float s[32][33];
    int b = blockIdx.z, c0 = blockIdx.y * 32, p0 = blockIdx.x * 32;
    int tx = threadIdx.x, ty = threadIdx.y;
    float val = x[((size_t)(b * NC + c0 + ty)) * NHW + p0 + tx];
    s[ty][tx] = val;
#pragma unroll
    for (int a = 0; a < NANG; a++) {
        float r = val * g_A[a * NHW + p0 + tx];
#pragma unroll
        for (int o = 16; o; o >>= 1) r += __shfl_xor_sync(0xffffffffu, r, o);
        if (tx == 0)
            g_mpart[((size_t)((a * NB + b) * NC + c0 + ty)) * NPT + blockIdx.x] = r;
    }
    __syncthreads();
    g_xnhwc[((size_t)b * NHW + p0 + ty) * NC + c0 + tx] = s[tx][ty];
}

__global__ void k_mean_reduce() {
    int wid = blockIdx.x * 8 + (threadIdx.x >> 5);
    int lane = threadIdx.x & 31;
    const float4* src = (const float4*)(g_mpart + (size_t)wid * NPT);
    float s = 0.f;
#pragma unroll
    for (int i = 0; i < NPT / 128; i++) {
        float4 v = src[i * 32 + lane];
        s += (v.x + v.y) + (v.z + v.w);
    }
#pragma unroll
    for (int o = 16; o; o >>= 1) s += __shfl_xor_sync(0xffffffffu, s, o);
    if (lane == 0) g_mean[wid] = s;
}

// Channel attention: mean -> w1 -> BN -> relu -> w2 -> sigmoid.
__global__ void k_chatt(const float* __restrict__ w1, const float* __restrict__ bng,
                        const float* __restrict__ bnb, const float* __restrict__ bnm,
                        const float* __restrict__ bnv, const float* __restrict__ w2) {
    __shared__ float sm[NC];
    __shared__ float sh[NMID];
    int ab = blockIdx.x;
    int tid = threadIdx.x;
    sm[tid] = g_mean[ab * NC + tid];
    __syncthreads();
    if (tid < NMID) {
        float hv = 0.f;
        const float* w1r = w1 + tid * NC;
        for (int c = 0; c < NC; c++) hv = fmaf(sm[c], w1r[c], hv);
        hv = (hv - bnm[tid]) * rsqrtf(bnv[tid] + 1e-5f) * bng[tid] + bnb[tid];
        sh[tid] = fmaxf(hv, 0.f);
    }
    __syncthreads();
    float cv = 0.f;
    const float* w2r = w2 + tid * NMID;
    for (int j = 0; j < NMID; j++) cv = fmaf(sh[j], w2r[j], cv);
    g_ca[ab * NC + tid] = sigm(cv);
}

// Per (angle,batch,pixel): channel-attended rotated value stats (avg, max over C).
__global__ void k_avgmax() {
    int w = blockIdx.x * 8 + (threadIdx.x >> 5);
    int lane = threadIdx.x & 31;
    int a = w >> 17;
    int b = (w >> 14) & 7;
    int p = w & (NHW - 1);
    float c_ = g_trig[2 * a], s_ = g_trig[2 * a + 1];
    float X = ncoord(p & 127), Y = ncoord(p >> 7);
    float gx = c_ * X - s_ * Y, gy = s_ * X + c_ * Y;
    float4 xr0, xr1;
    gather_xr(b, (gx + 1.0f) * 63.5f, (gy + 1.0f) * 63.5f, lane, xr0, xr1);
    const float4* car = (const float4*)(g_ca + (size_t)(a * NB + b) * NC);
    float4 ca0 = car[lane], ca1 = car[lane + 32];
    float v0 = ca0.x * xr0.x, v1 = ca0.y * xr0.y, v2 = ca0.z * xr0.z, v3 = ca0.w * xr0.w;
    float v4 = ca1.x * xr1.x, v5 = ca1.y * xr1.y, v6 = ca1.z * xr1.z, v7 = ca1.w * xr1.w;
    float sum = ((v0 + v1) + (v2 + v3)) + ((v4 + v5) + (v6 + v7));
    float mx = fmaxf(fmaxf(fmaxf(v0, v1), fmaxf(v2, v3)),
                     fmaxf(fmaxf(v4, v5), fmaxf(v6, v7)));
#pragma unroll
    for (int o = 16; o; o >>= 1) {
        sum += __shfl_xor_sync(0xffffffffu, sum, o);
        mx = fmaxf(mx, __shfl_xor_sync(0xffffffffu, mx, o));
    }
    if (lane == 0) {
        g_avg[w] = sum * (1.0f / (float)NC);
        g_maxm[w] = mx;
    }
}

// 7x7 conv over (avg,max) with pad 3, then sigmoid -> sa.
__global__ void k_conv(const float* __restrict__ wsp) {
    __shared__ float sw[98];
    int tid = threadIdx.x;
    if (tid < 98) sw[tid] = wsp[tid];
    __syncthreads();
    int id = blockIdx.x * 256 + tid;
    int ab = id >> 14;
    int p = id & (NHW - 1);
    int py = p >> 7, px = p & 127;
    const float* av = g_avg + (size_t)ab * NHW;
    const float* mxp = g_maxm + (size_t)ab * NHW;
    float acc = 0.f;
#pragma unroll
    for (int ky = 0; ky < 7; ky++) {
        int yy = py + ky - 3;
        if ((unsigned)yy < 128u) {
#pragma unroll
            for (int kx = 0; kx < 7; kx++) {
                int xx = px + kx - 3;
                if ((unsigned)xx < 128u) {
                    int q = yy * NW + xx;
                    acc = fmaf(sw[ky * 7 + kx], av[q], acc);
                    acc = fmaf(sw[49 + ky * 7 + kx], mxp[q], acc);
                }
            }
        }
    }
    g_sa[id] = sigm(acc);
}

// Fully fused inverse pass with gather dedup:
// out[q] = (1/4) * sum_a ca_a (.) sum_cell w_cell(a,q) * x[cell],
// w_cell = sum_j wi_j * sa[p_j] * tent(fwd(p_j) - cell) over the 4 inverse
// corners p_j; cells live in a 4x4 window (fwd positions of a 2x2 patch span
// <= sqrt(2)). Cell weights computed one-per-lane, broadcast by shfl.
// Block = 32 warps = 32 consecutive pixels of one row; smem transpose lets us
// write NCHW d_out directly (no NHWC roundtrip).
__global__ void __launch_bounds__(1024, 1) k_fused(float* __restrict__ out) {
    __shared__ float s[32][264];
    int b = blockIdx.x >> 9;            // 512 tiles per image
    int q0 = (blockIdx.x & 511) * 32;
    int wid = threadIdx.x >> 5, lane = threadIdx.x & 31;
    int q = q0 + wid;
    float X = ncoord(q & 127), Y = ncoord(q >> 7);
    float4 acc0 = make_float4(0.f, 0.f, 0.f, 0.f), acc1 = acc0;

#pragma unroll
    for (int a = 0; a < NANG; a++) {
        float c_ = g_trig[2 * a], s_ = g_trig[2 * a + 1];
        // inverse grid position
        float gx = c_ * X + s_ * Y, gy = -s_ * X + c_ * Y;
        float ixv = (gx + 1.0f) * 63.5f, iyv = (gy + 1.0f) * 63.5f;
        float x0 = floorf(ixv), y0 = floorf(iyv);
        float wx1 = ixv - x0, wx0 = 1.0f - wx1;
        float wy1 = iyv - y0, wy0 = 1.0f - wy1;

        float fxj[4], fyj[4], wj[4];
        float minfx = 1e9f, minfy = 1e9f;
#pragma unroll
        for (int j = 0; j < 4; j++) {
            float fpx = x0 + (float)(j & 1);
            float fpy = y0 + (float)(j >> 1);
            float wi = ((j & 1) ? wx1 : wx0) * ((j >> 1) ? wy1 : wy0);
            wj[j] = 0.f; fxj[j] = 1e9f; fyj[j] = 1e9f;
            if (fpx >= 0.f && fpx <= 127.f && fpy >= 0.f && fpy <= 127.f && wi > WEPS) {
                int ip = (int)fpy * NW + (int)fpx;
                float sav = g_sa[(size_t)(a * NB + b) * NHW + ip];
                float Xp = ncoord((int)fpx), Yp = ncoord((int)fpy);
                float fgx = c_ * Xp - s_ * Yp, fgy = s_ * Xp + c_ * Yp;
                fxj[j] = (fgx + 1.0f) * 63.5f;
                fyj[j] = (fgy + 1.0f) * 63.5f;
                wj[j] = wi * sav;
                minfx = fminf(minfx, fxj[j]);
                minfy = fminf(minfy, fyj[j]);
            }
        }
        if (minfx < 500.f) {
            int bx = (int)floorf(minfx), by = (int)floorf(minfy);
            // lane l (<16) computes the weight of cell (bx + l&3, by + l>>2)
            float cellx = (float)(bx + (lane & 3));
            float celly = (float)(by + ((lane >> 2) & 3));
            float wc = 0.f;
#pragma unroll
            for (int j = 0; j < 4; j++) {
                float tx = fmaxf(0.f, 1.0f - fabsf(fxj[j] - cellx));
                float ty = fmaxf(0.f, 1.0f - fabsf(fyj[j] - celly));
                wc = fmaf(wj[j], tx * ty, wc);
            }
            float4 t0 = make_float4(0.f, 0.f, 0.f, 0.f), t1 = t0;
#pragma unroll
            for (int k = 0; k < 16; k++) {
                float w = __shfl_sync(0xffffffffu, wc, k);
                int cxk = bx + (k & 3), cyk = by + (k >> 2);
                if (w > WEPS && (unsigned)cxk < 128u && (unsigned)cyk < 128u) {
                    const float4* row = (const float4*)(g_xnhwc +
                        ((size_t)b * NHW + cyk * NW + cxk) * NC);
                    fma4(t0, w, row[lane]);
                    fma4(t1, w, row[lane + 32]);
                }
            }
            const float4* car = (const float4*)(g_ca + (size_t)(a * NB + b) * NC);
            fma44(acc0, car[lane], t0);
            fma44(acc1, car[lane + 32], t1);
        }
    }

    // smem transpose -> NCHW coalesced stores (with /4 folded in)
    float4* srow = (float4*)&s[wid][0];
    srow[lane] = acc0;
    srow[lane + 32] = acc1;
    __syncthreads();
#pragma unroll
    for (int it = 0; it < 2; it++) {
        int c0 = (wid + 32 * it) * 4;
        float4 v = *(const float4*)&s[lane][c0];
        size_t base = ((size_t)(b * NC + c0)) * NHW + q0 + lane;
        out[base]           = v.x * 0.25f;
        out[base + NHW]     = v.y * 0.25f;
        out[base + 2 * NHW] = v.z * 0.25f;
        out[base + 3 * NHW] = v.w * 0.25f;
    }
}

// ---------------- launch ----------------
extern "C" void kernel_launch(void* const* d_in, const int* in_sizes, int n_in,
                              void* d_out, int out_size) {
    const float* x      = (const float*)d_in[0];
    const float* angles = (const float*)d_in[1];
    const float* w1     = (const float*)d_in[2];
    const float* bng    = (const float*)d_in[3];
    const float* bnb    = (const float*)d_in[4];
    const float* bnm    = (const float*)d_in[5];
    const float* bnv    = (const float*)d_in[6];
    const float* w2     = (const float*)d_in[7];
    const float* wsp    = (const float*)d_in[8];
    float* out = (float*)d_out;

    dim3 tb(32, 32);
    k_trig<<<1, 32>>>(angles);
    k_Amap<<<(NANG * NHW) / 256, 256>>>();
    k_transpose_mean<<<dim3(NPT, NC / 32, NB), tb>>>(x);
    k_mean_reduce<<<(NANG * NB * NC) / 8, 256>>>();
    k_chatt<<<NANG * NB, 256>>>(w1, bng, bnb, bnm, bnv, w2);
    k_avgmax<<<(NANG * NB * NHW) / 8, 256>>>();
    k_conv<<<(NANG * NB * NHW) / 256, 256>>>(wsp);
    k_fused<<<NB * NHW / 32, 1024>>>(out);
}

// round 5
// speedup vs baseline: 1.2502x; 1.1855x over previous
#include <cuda_runtime.h>
#include <cuda_fp16.h>
#include <math.h>

#define NB   8
#define NC   256
#define NH   128
#define NW   128
#define NHW  16384
#define NMID 64
#define NANG 4
#define NPT  512
#define WEPS 1e-5f

// ---------------- scratch (static __device__, no allocations) ----------------
__device__ __half g_xh[(size_t)NB * NHW * NC];     // 67 MB  x in NHWC fp16
__device__ float g_trig[2 * NANG];
__device__ float g_A[NANG * NHW];
__device__ float g_mpart[(size_t)NANG * NB * NC * NPT];
__device__ float g_mean[NANG * NB * NC];
__device__ float g_ca[NANG * NB * NC];
__device__ float g_avg[(size_t)NANG * NB * NHW];
__device__ float g_maxm[(size_t)NANG * NB * NHW];
__device__ float g_sa[(size_t)NANG * NB * NHW];

// ---------------- helpers ----------------
__device__ __forceinline__ float ncoord(int j) { return -1.0f + (float)j * (2.0f / 127.0f); }
__device__ __forceinline__ float sigm(float v) { return 1.0f / (1.0f + expf(-v)); }

// Accumulate w * row8 (8 fp16 channels for this lane) into acc[8].
__device__ __forceinline__ void acc_row(float* acc, float w, const uint4 h) {
    const __half2* hp = (const __half2*)&h;
#pragma unroll
    for (int i = 0; i < 4; i++) {
        float2 f = __half22float2(hp[i]);
        acc[2 * i]     = fmaf(w, f.x, acc[2 * i]);
        acc[2 * i + 1] = fmaf(w, f.y, acc[2 * i + 1]);
    }
}

// Bilinear gather into 8 fp32 channel accumulators (channels lane*8..lane*8+7).
// Warp-uniform control flow; sub-WEPS weights skipped.
__device__ __forceinline__ void gather8(int b, float fix, float fiy, int lane, float* acc) {
#pragma unroll
    for (int i = 0; i < 8; i++) acc[i] = 0.f;
    float fx0 = floorf(fix), fy0 = floorf(fiy);
    float wx1 = fix - fx0, wx0 = 1.0f - wx1;
    float wy1 = fiy - fy0, wy0 = 1.0f - wy1;
    float cx[4] = {fx0, fx0 + 1.0f, fx0,        fx0 + 1.0f};
    float cy[4] = {fy0, fy0,        fy0 + 1.0f, fy0 + 1.0f};
    float cw[4] = {wx0 * wy0, wx1 * wy0, wx0 * wy1, wx1 * wy1};
#pragma unroll
    for (int k = 0; k < 4; k++) {
        float fx = cx[k], fy = cy[k], wv = cw[k];
        if (fx >= 0.f && fx <= 127.f && fy >= 0.f && fy <= 127.f && wv > WEPS) {
            const uint4* row = (const uint4*)(g_xh +
                ((size_t)b * NHW + (int)fy * NW + (int)fx) * NC);
            acc_row(acc, wv, row[lane]);
        }
    }
}

// ---------------- kernels ----------------

__global__ void k_trig(const float* __restrict__ angles) {
    int i = threadIdx.x;
    if (i < NANG) {
        float a = angles[i];
        g_trig[2 * i]     = cosf(a);
        g_trig[2 * i + 1] = sinf(a);
    }
}

__global__ void k_Amap() {
    int id = blockIdx.x * 256 + threadIdx.x;
    if (id >= NANG * NHW) return;
    int a = id / NHW, src = id % NHW;
    int sy = src >> 7, sx = src & 127;
    float c_ = g_trig[2 * a], s_ = g_trig[2 * a + 1];
    float dx = (float)sx - 63.5f, dy = (float)sy - 63.5f;
    float pxf = c_ * dx + s_ * dy + 63.5f;
    float pyf = -s_ * dx + c_ * dy + 63.5f;
    int px0 = (int)floorf(pxf + 0.5f) - 2;
    int py0 = (int)floorf(pyf + 0.5f) - 2;
    float acc = 0.f;
    for (int py = py0; py < py0 + 5; py++) {
        for (int px = px0; px < px0 + 5; px++) {
            if ((unsigned)px < 128u && (unsigned)py < 128u) {
                float X = ncoord(px), Y = ncoord(py);
                float gx = c_ * X - s_ * Y, gy = s_ * X + c_ * Y;
                float ix = (gx + 1.0f) * 63.5f, iy = (gy + 1.0f) * 63.5f;
                float tx = 1.0f - fabsf(ix - (float)sx);
                float ty = 1.0f - fabsf(iy - (float)sy);
                if (tx > 0.f && ty > 0.f) acc += tx * ty;
            }
        }
    }
    g_A[id] = acc * (1.0f / (float)NHW);
}

// NCHW -> NHWC(fp16) transpose fused with per-angle weighted-mean partials (fp32).
__global__ void k_transpose_mean(const float* __restrict__ x) {
    __shared__ float s[32][33];
    int b = blockIdx.z, c0 = blockIdx.y * 32, p0 = blockIdx.x * 32;
    int tx = threadIdx.x, ty = threadIdx.y;
    float val = x[((size_t)(b * NC + c0 + ty)) * NHW + p0 + tx];
    s[ty][tx] = val;
#pragma unroll
    for (int a = 0; a < NANG; a++) {
        float r = val * g_A[a * NHW + p0 + tx];
#pragma unroll
        for (int o = 16; o; o >>= 1) r += __shfl_xor_sync(0xffffffffu, r, o);
        if (tx == 0)
            g_mpart[((size_t)((a * NB + b) * NC + c0 + ty)) * NPT + blockIdx.x] = r;
    }
    __syncthreads();
    g_xh[((size_t)b * NHW + p0 + ty) * NC + c0 + tx] = __float2half_rn(s[tx][ty]);
}

__global__ void k_mean_reduce() {
    int wid = blockIdx.x * 8 + (threadIdx.x >> 5);
    int lane = threadIdx.x & 31;
    const float4* src = (const float4*)(g_mpart + (size_t)wid * NPT);
    float s = 0.f;
#pragma unroll
    for (int i = 0; i < NPT / 128; i++) {
        float4 v = src[i * 32 + lane];
        s += (v.x + v.y) + (v.z + v.w);
    }
#pragma unroll
    for (int o = 16; o; o >>= 1) s += __shfl_xor_sync(0xffffffffu, s, o);
    if (lane == 0) g_mean[wid] = s;
}

__global__ void k_chatt(const float* __restrict__ w1, const float* __restrict__ bng,
                        const float* __restrict__ bnb, const float* __restrict__ bnm,
                        const float* __restrict__ bnv, const float* __restrict__ w2) {
    __shared__ float sm[NC];
    __shared__ float sh[NMID];
    int ab = blockIdx.x;
    int tid = threadIdx.x;
    sm[tid] = g_mean[ab * NC + tid];
    __syncthreads();
    if (tid < NMID) {
        float hv = 0.f;
        const float* w1r = w1 + tid * NC;
        for (int c = 0; c < NC; c++) hv = fmaf(sm[c], w1r[c], hv);
        hv = (hv - bnm[tid]) * rsqrtf(bnv[tid] + 1e-5f) * bng[tid] + bnb[tid];
        sh[tid] = fmaxf(hv, 0.f);
    }
    __syncthreads();
    float cv = 0.f;
    const float* w2r = w2 + tid * NMID;
    for (int j = 0; j < NMID; j++) cv = fmaf(sh[j], w2r[j], cv);
    g_ca[ab * NC + tid] = sigm(cv);
}

// Per (angle,batch,pixel) channel-attended rotated stats. 1 warp / pixel.
__global__ void k_avgmax() {
    int w = blockIdx.x * 8 + (threadIdx.x >> 5);
    int lane = threadIdx.x & 31;
    int a = w >> 17;
    int b = (w >> 14) & 7;
    int p = w & (NHW - 1);
    float c_ = g_trig[2 * a], s_ = g_trig[2 * a + 1];
    float X = ncoord(p & 127), Y = ncoord(p >> 7);
    float gx = c_ * X - s_ * Y, gy = s_ * X + c_ * Y;
    float acc[8];
    gather8(b, (gx + 1.0f) * 63.5f, (gy + 1.0f) * 63.5f, lane, acc);
    const float4* car = (const float4*)(g_ca + (size_t)(a * NB + b) * NC);
    float4 ca0 = car[lane * 2], ca1 = car[lane * 2 + 1];
    float v0 = ca0.x * acc[0], v1 = ca0.y * acc[1], v2 = ca0.z * acc[2], v3 = ca0.w * acc[3];
    float v4 = ca1.x * acc[4], v5 = ca1.y * acc[5], v6 = ca1.z * acc[6], v7 = ca1.w * acc[7];
    float sum = ((v0 + v1) + (v2 + v3)) + ((v4 + v5) + (v6 + v7));
    float mx = fmaxf(fmaxf(fmaxf(v0, v1), fmaxf(v2, v3)),
                     fmaxf(fmaxf(v4, v5), fmaxf(v6, v7)));
#pragma unroll
    for (int o = 16; o; o >>= 1) {
        sum += __shfl_xor_sync(0xffffffffu, sum, o);
        mx = fmaxf(mx, __shfl_xor_sync(0xffffffffu, mx, o));
    }
    if (lane == 0) {
        g_avg[w] = sum * (1.0f / (float)NC);
        g_maxm[w] = mx;
    }
}

__global__ void k_conv(const float* __restrict__ wsp) {
    __shared__ float sw[98];
    int tid = threadIdx.x;
    if (tid < 98) sw[tid] = wsp[tid];
    __syncthreads();
    int id = blockIdx.x * 256 + tid;
    int ab = id >> 14;
    int p = id & (NHW - 1);
    int py = p >> 7, px = p & 127;
    const float* av = g_avg + (size_t)ab * NHW;
    const float* mxp = g_maxm + (size_t)ab * NHW;
    float acc = 0.f;
#pragma unroll
    for (int ky = 0; ky < 7; ky++) {
        int yy = py + ky - 3;
        if ((unsigned)yy < 128u) {
#pragma unroll
            for (int kx = 0; kx < 7; kx++) {
                int xx = px + kx - 3;
                if ((unsigned)xx < 128u) {
                    int q = yy * NW + xx;
                    acc = fmaf(sw[ky * 7 + kx], av[q], acc);
                    acc = fmaf(sw[49 + ky * 7 + kx], mxp[q], acc);
                }
            }
        }
    }
    g_sa[id] = sigm(acc);
}

// Fused inverse pass with composed-gather dedup. 512 threads = 16 warps = 16
// consecutive pixels of one row (128-reg budget, no spills). Per angle, the
// 16 (inv x fwd) corners collapse to <=16 cells of a 4x4 window; cell weights
// computed one-per-lane and broadcast by shfl. smem transpose -> direct NCHW
// stores (64B-contiguous per half-warp) with /4 folded in.
__global__ void __launch_bounds__(512) k_fused(float* __restrict__ out) {
    __shared__ float s[16][260];
    int b = blockIdx.x >> 10;            // 1024 16-pixel tiles per image
    int q0 = (blockIdx.x & 1023) * 16;
    int wid = threadIdx.x >> 5, lane = threadIdx.x & 31;
    int q = q0 + wid;
    float X = ncoord(q & 127), Y = ncoord(q >> 7);
    float res[8];
#pragma unroll
    for (int i = 0; i < 8; i++) res[i] = 0.f;

#pragma unroll
    for (int a = 0; a < NANG; a++) {
        float c_ = g_trig[2 * a], s_ = g_trig[2 * a + 1];
        float gx = c_ * X + s_ * Y, gy = -s_ * X + c_ * Y;   // inverse grid
        float ixv = (gx + 1.0f) * 63.5f, iyv = (gy + 1.0f) * 63.5f;
        float x0 = floorf(ixv), y0 = floorf(iyv);
        float wx1 = ixv - x0, wx0 = 1.0f - wx1;
        float wy1 = iyv - y0, wy0 = 1.0f - wy1;

        float fxj[4], fyj[4], wj[4];
        float minfx = 1e9f, minfy = 1e9f;
#pragma unroll
        for (int j = 0; j < 4; j++) {
            float fpx = x0 + (float)(j & 1);
            float fpy = y0 + (float)(j >> 1);
            float wi = ((j & 1) ? wx1 : wx0) * ((j >> 1) ? wy1 : wy0);
            wj[j] = 0.f; fxj[j] = 1e9f; fyj[j] = 1e9f;
            if (fpx >= 0.f && fpx <= 127.f && fpy >= 0.f && fpy <= 127.f && wi > WEPS) {
                int ip = (int)fpy * NW + (int)fpx;
                float sav = g_sa[(size_t)(a * NB + b) * NHW + ip];
                float Xp = ncoord((int)fpx), Yp = ncoord((int)fpy);
                float fgx = c_ * Xp - s_ * Yp, fgy = s_ * Xp + c_ * Yp;
                fxj[j] = (fgx + 1.0f) * 63.5f;
                fyj[j] = (fgy + 1.0f) * 63.5f;
                wj[j] = wi * sav;
                minfx = fminf(minfx, fxj[j]);
                minfy = fminf(minfy, fyj[j]);
            }
        }
        if (minfx < 500.f) {
            int bx = (int)floorf(minfx), by = (int)floorf(minfy);
            float cellx = (float)(bx + (lane & 3));
            float celly = (float)(by + ((lane >> 2) & 3));
            float wc = 0.f;
#pragma unroll
            for (int j = 0; j < 4; j++) {
                float tx = fmaxf(0.f, 1.0f - fabsf(fxj[j] - cellx));
                float ty = fmaxf(0.f, 1.0f - fabsf(fyj[j] - celly));
                wc = fmaf(wj[j], tx * ty, wc);
            }
            float t[8];
#pragma unroll
            for (int i = 0; i < 8; i++) t[i] = 0.f;
#pragma unroll
            for (int k = 0; k < 16; k++) {
                float w = __shfl_sync(0xffffffffu, wc, k);
                int cxk = bx + (k & 3), cyk = by + (k >> 2);
                if (w > WEPS && (unsigned)cxk < 128u && (unsigned)cyk < 128u) {
                    const uint4* row = (const uint4*)(g_xh +
                        ((size_t)b * NHW + cyk * NW + cxk) * NC);
                    acc_row(t, w, row[lane]);
                }
            }
            const float4* car = (const float4*)(g_ca + (size_t)(a * NB + b) * NC);
            float4 ca0 = car[lane * 2], ca1 = car[lane * 2 + 1];
            res[0] = fmaf(ca0.x, t[0], res[0]); res[1] = fmaf(ca0.y, t[1], res[1]);
            res[2] = fmaf(ca0.z, t[2], res[2]); res[3] = fmaf(ca0.w, t[3], res[3]);
            res[4] = fmaf(ca1.x, t[4], res[4]); res[5] = fmaf(ca1.y, t[5], res[5]);
            res[6] = fmaf(ca1.z, t[6], res[6]); res[7] = fmaf(ca1.w, t[7], res[7]);
        }
    }

    // smem transpose: s[pixel][channel]
    *(float4*)&s[wid][lane * 8]     = make_float4(res[0], res[1], res[2], res[3]);
    *(float4*)&s[wid][lane * 8 + 4] = make_float4(res[4], res[5], res[6], res[7]);
    __syncthreads();
    // warp wid covers channels [wid*16, wid*16+16); half-warps split them.
    int pix = lane & 15, hl = lane >> 4;
#pragma unroll
    for (int it = 0; it < 8; it++) {
        int c = wid * 16 + hl * 8 + it;
        float v = s[pix][c];
        out[((size_t)(b * NC + c)) * NHW + q0 + pix] = v * 0.25f;
    }
}

// ---------------- launch ----------------
extern "C" void kernel_launch(void* const* d_in, const int* in_sizes, int n_in,
                              void* d_out, int out_size) {
    const float* x      = (const float*)d_in[0];
    const float* angles = (const float*)d_in[1];
    const float* w1     = (const float*)d_in[2];
    const float* bng    = (const float*)d_in[3];
    const float* bnb    = (const float*)d_in[4];
    const float* bnm    = (const float*)d_in[5];
    const float* bnv    = (const float*)d_in[6];
    const float* w2     = (const float*)d_in[7];
    const float* wsp    = (const float*)d_in[8];
    float* out = (float*)d_out;

    dim3 tb(32, 32);
    k_trig<<<1, 32>>>(angles);
    k_Amap<<<(NANG * NHW) / 256, 256>>>();
    k_transpose_mean<<<dim3(NPT, NC / 32, NB), tb>>>(x);
    k_mean_reduce<<<(NANG * NB * NC) / 8, 256>>>();
    k_chatt<<<NANG * NB, 256>>>(w1, bng, bnb, bnm, bnv, w2);
    k_avgmax<<<(NANG * NB * NHW) / 8, 256>>>();
    k_conv<<<(NANG * NB * NHW) / 256, 256>>>(wsp);
    k_fused<<<NB * NHW / 16, 512>>>(out);
}

// round 6
// speedup vs baseline: 1.3737x; 1.0988x over previous
#include <cuda_runtime.h>
#include <cuda_fp16.h>
#include <math.h>

#define NB   8
#define NC   256
#define NH   128
#define NW   128
#define NHW  16384
#define NMID 64
#define NANG 4
#define NPT  512
#define WEPS 1e-5f

// ---------------- scratch (static __device__, no allocations) ----------------
__device__ __half g_xh[(size_t)NB * NHW * NC];     // 67 MB  x in NHWC fp16
__device__ float g_trig[2 * NANG];
__device__ float g_A[NANG * NHW];
__device__ float g_mpart[(size_t)NANG * NB * NC * NPT];
__device__ float g_mean[NANG * NB * NC];
__device__ float g_ca[NANG * NB * NC];
__device__ float g_avg[(size_t)NANG * NB * NHW];
__device__ float g_maxm[(size_t)NANG * NB * NHW];
__device__ float g_sa[(size_t)NANG * NB * NHW];

// ---------------- helpers ----------------
__device__ __forceinline__ float ncoord(int j) { return -1.0f + (float)j * (2.0f / 127.0f); }
__device__ __forceinline__ float sigm(float v) { return 1.0f / (1.0f + expf(-v)); }

// Accumulate w * row8 (8 fp16 channels for this lane) into acc[8].
__device__ __forceinline__ void acc_row(float* acc, float w, const uint4 h) {
    const __half2* hp = (const __half2*)&h;
#pragma unroll
    for (int i = 0; i < 4; i++) {
        float2 f = __half22float2(hp[i]);
        acc[2 * i]     = fmaf(w, f.x, acc[2 * i]);
        acc[2 * i + 1] = fmaf(w, f.y, acc[2 * i + 1]);
    }
}

// Bilinear gather into 8 fp32 channel accumulators (channels lane*8..lane*8+7).
__device__ __forceinline__ void gather8(int b, float fix, float fiy, int lane, float* acc) {
#pragma unroll
    for (int i = 0; i < 8; i++) acc[i] = 0.f;
    float fx0 = floorf(fix), fy0 = floorf(fiy);
    float wx1 = fix - fx0, wx0 = 1.0f - wx1;
    float wy1 = fiy - fy0, wy0 = 1.0f - wy1;
    float cx[4] = {fx0, fx0 + 1.0f, fx0,        fx0 + 1.0f};
    float cy[4] = {fy0, fy0,        fy0 + 1.0f, fy0 + 1.0f};
    float cw[4] = {wx0 * wy0, wx1 * wy0, wx0 * wy1, wx1 * wy1};
#pragma unroll
    for (int k = 0; k < 4; k++) {
        float fx = cx[k], fy = cy[k], wv = cw[k];
        if (fx >= 0.f && fx <= 127.f && fy >= 0.f && fy <= 127.f && wv > WEPS) {
            const uint4* row = (const uint4*)(g_xh +
                ((size_t)b * NHW + (int)fy * NW + (int)fx) * NC);
            acc_row(acc, wv, row[lane]);
        }
    }
}

// ---------------- kernels ----------------

__global__ void k_trig(const float* __restrict__ angles) {
    int i = threadIdx.x;
    if (i < NANG) {
        float a = angles[i];
        g_trig[2 * i]     = cosf(a);
        g_trig[2 * i + 1] = sinf(a);
    }
}

__global__ void k_Amap() {
    int id = blockIdx.x * 256 + threadIdx.x;
    if (id >= NANG * NHW) return;
    int a = id / NHW, src = id % NHW;
    int sy = src >> 7, sx = src & 127;
    float c_ = g_trig[2 * a], s_ = g_trig[2 * a + 1];
    float dx = (float)sx - 63.5f, dy = (float)sy - 63.5f;
    float pxf = c_ * dx + s_ * dy + 63.5f;
    float pyf = -s_ * dx + c_ * dy + 63.5f;
    int px0 = (int)floorf(pxf + 0.5f) - 2;
    int py0 = (int)floorf(pyf + 0.5f) - 2;
    float acc = 0.f;
    for (int py = py0; py < py0 + 5; py++) {
        for (int px = px0; px < px0 + 5; px++) {
            if ((unsigned)px < 128u && (unsigned)py < 128u) {
                float X = ncoord(px), Y = ncoord(py);
                float gx = c_ * X - s_ * Y, gy = s_ * X + c_ * Y;
                float ix = (gx + 1.0f) * 63.5f, iy = (gy + 1.0f) * 63.5f;
                float tx = 1.0f - fabsf(ix - (float)sx);
                float ty = 1.0f - fabsf(iy - (float)sy);
                if (tx > 0.f && ty > 0.f) acc += tx * ty;
            }
        }
    }
    g_A[id] = acc * (1.0f / (float)NHW);
}

// NCHW -> NHWC(fp16) transpose (64-channel tiles, half2 stores) fused with
// per-angle weighted-mean partials (fp32).
__global__ void k_transpose_mean(const float* __restrict__ x) {
    __shared__ float s[64][33];
    int b = blockIdx.z, c0 = blockIdx.y * 64, p0 = blockIdx.x * 32;
    int tx = threadIdx.x, ty = threadIdx.y;
    float v0 = x[((size_t)(b * NC + c0 + ty)) * NHW + p0 + tx];
    float v1 = x[((size_t)(b * NC + c0 + 32 + ty)) * NHW + p0 + tx];
    s[ty][tx] = v0;
    s[ty + 32][tx] = v1;
#pragma unroll
    for (int a = 0; a < NANG; a++) {
        float Aw = g_A[a * NHW + p0 + tx];
        float r0 = v0 * Aw, r1 = v1 * Aw;
#pragma unroll
        for (int o = 16; o; o >>= 1) {
            r0 += __shfl_xor_sync(0xffffffffu, r0, o);
            r1 += __shfl_xor_sync(0xffffffffu, r1, o);
        }
        if (tx == 0) {
            size_t base = ((size_t)((a * NB + b) * NC + c0 + ty)) * NPT + blockIdx.x;
            g_mpart[base] = r0;
            g_mpart[base + (size_t)32 * NPT] = r1;
        }
    }
    __syncthreads();
    // thread (ty,tx): pixel p0+ty, channels c0+2tx, c0+2tx+1 -> one half2 (128B/warp)
    __half2 h2 = __floats2half2_rn(s[2 * tx][ty], s[2 * tx + 1][ty]);
    *(__half2*)(g_xh + ((size_t)b * NHW + p0 + ty) * NC + c0 + 2 * tx) = h2;
}

__global__ void k_mean_reduce() {
    int wid = blockIdx.x * 8 + (threadIdx.x >> 5);
    int lane = threadIdx.x & 31;
    const float4* src = (const float4*)(g_mpart + (size_t)wid * NPT);
    float s = 0.f;
#pragma unroll
    for (int i = 0; i < NPT / 128; i++) {
        float4 v = src[i * 32 + lane];
        s += (v.x + v.y) + (v.z + v.w);
    }
#pragma unroll
    for (int o = 16; o; o >>= 1) s += __shfl_xor_sync(0xffffffffu, s, o);
    if (lane == 0) g_mean[wid] = s;
}

__global__ void k_chatt(const float* __restrict__ w1, const float* __restrict__ bng,
                        const float* __restrict__ bnb, const float* __restrict__ bnm,
                        const float* __restrict__ bnv, const float* __restrict__ w2) {
    __shared__ float sm[NC];
    __shared__ float sh[NMID];
    int ab = blockIdx.x;
    int tid = threadIdx.x;
    sm[tid] = g_mean[ab * NC + tid];
    __syncthreads();
    if (tid < NMID) {
        float hv = 0.f;
        const float* w1r = w1 + tid * NC;
        for (int c = 0; c < NC; c++) hv = fmaf(sm[c], w1r[c], hv);
        hv = (hv - bnm[tid]) * rsqrtf(bnv[tid] + 1e-5f) * bng[tid] + bnb[tid];
        sh[tid] = fmaxf(hv, 0.f);
    }
    __syncthreads();
    float cv = 0.f;
    const float* w2r = w2 + tid * NMID;
    for (int j = 0; j < NMID; j++) cv = fmaf(sh[j], w2r[j], cv);
    g_ca[ab * NC + tid] = sigm(cv);
}

// Channel-attended rotated stats; 2 adjacent pixels per warp (MLP 8).
__global__ void k_avgmax() {
    int w2 = blockIdx.x * 8 + (threadIdx.x >> 5);
    int lane = threadIdx.x & 31;
    int a = w2 >> 16;                 // NB*NHW/2 = 65536
    int b = (w2 >> 13) & 7;
    int p = (w2 & 8191) * 2;
    float c_ = g_trig[2 * a], s_ = g_trig[2 * a + 1];
    float X0 = ncoord(p & 127), X1 = ncoord((p & 127) + 1), Y = ncoord(p >> 7);
    float acc0[8], acc1[8];
    {
        float gx = c_ * X0 - s_ * Y, gy = s_ * X0 + c_ * Y;
        gather8(b, (gx + 1.0f) * 63.5f, (gy + 1.0f) * 63.5f, lane, acc0);
    }
    {
        float gx = c_ * X1 - s_ * Y, gy = s_ * X1 + c_ * Y;
        gather8(b, (gx + 1.0f) * 63.5f, (gy + 1.0f) * 63.5f, lane, acc1);
    }
    const float4* car = (const float4*)(g_ca + (size_t)(a * NB + b) * NC);
    float4 ca0 = car[lane * 2], ca1 = car[lane * 2 + 1];
    float cav[8] = {ca0.x, ca0.y, ca0.z, ca0.w, ca1.x, ca1.y, ca1.z, ca1.w};
    float sum0 = 0.f, mx0 = -1e30f, sum1 = 0.f, mx1 = -1e30f;
#pragma unroll
    for (int i = 0; i < 8; i++) {
        float u = cav[i] * acc0[i], v = cav[i] * acc1[i];
        sum0 += u; mx0 = fmaxf(mx0, u);
        sum1 += v; mx1 = fmaxf(mx1, v);
    }
#pragma unroll
    for (int o = 16; o; o >>= 1) {
        sum0 += __shfl_xor_sync(0xffffffffu, sum0, o);
        mx0 = fmaxf(mx0, __shfl_xor_sync(0xffffffffu, mx0, o));
        sum1 += __shfl_xor_sync(0xffffffffu, sum1, o);
        mx1 = fmaxf(mx1, __shfl_xor_sync(0xffffffffu, mx1, o));
    }
    if (lane == 0) {
        size_t base = (size_t)(a * NB + b) * NHW + p;
        g_avg[base]     = sum0 * (1.0f / (float)NC);
        g_avg[base + 1] = sum1 * (1.0f / (float)NC);
        g_maxm[base]     = mx0;
        g_maxm[base + 1] = mx1;
    }
}

__global__ void k_conv(const float* __restrict__ wsp) {
    __shared__ float sw[98];
    int tid = threadIdx.x;
    if (tid < 98) sw[tid] = wsp[tid];
    __syncthreads();
    int id = blockIdx.x * 256 + tid;
    int ab = id >> 14;
    int p = id & (NHW - 1);
    int py = p >> 7, px = p & 127;
    const float* av = g_avg + (size_t)ab * NHW;
    const float* mxp = g_maxm + (size_t)ab * NHW;
    float acc = 0.f;
#pragma unroll
    for (int ky = 0; ky < 7; ky++) {
        int yy = py + ky - 3;
        if ((unsigned)yy < 128u) {
#pragma unroll
            for (int kx = 0; kx < 7; kx++) {
                int xx = px + kx - 3;
                if ((unsigned)xx < 128u) {
                    int q = yy * NW + xx;
                    acc = fmaf(sw[ky * 7 + kx], av[q], acc);
                    acc = fmaf(sw[49 + ky * 7 + kx], mxp[q], acc);
                }
            }
        }
    }
    g_sa[id] = sigm(acc);
}

// Fused inverse pass with composed-gather dedup. 512 threads = 16 warps = 16
// consecutive pixels of one row. __launch_bounds__(512,2) caps regs at 64 ->
// 2 blocks/SM (8 warps/SMSP) for latency hiding; the corner loop is two-pass
// (recompute instead of keeping fxj/fyj/wj arrays live).
__global__ void __launch_bounds__(512, 2) k_fused(float* __restrict__ out) {
    __shared__ float s[16][260];
    int b = blockIdx.x >> 10;
    int q0 = (blockIdx.x & 1023) * 16;
    int wid = threadIdx.x >> 5, lane = threadIdx.x & 31;
    int q = q0 + wid;
    float X = ncoord(q & 127), Y = ncoord(q >> 7);
    float res[8];
#pragma unroll
    for (int i = 0; i < 8; i++) res[i] = 0.f;

#pragma unroll
    for (int a = 0; a < NANG; a++) {
        float c_ = g_trig[2 * a], s_ = g_trig[2 * a + 1];
        float gx = c_ * X + s_ * Y, gy = -s_ * X + c_ * Y;   // inverse grid
        float ixv = (gx + 1.0f) * 63.5f, iyv = (gy + 1.0f) * 63.5f;
        float x0 = floorf(ixv), y0 = floorf(iyv);
        float wx1 = ixv - x0, wx0 = 1.0f - wx1;
        float wy1 = iyv - y0, wy0 = 1.0f - wy1;

        // pass 1: bounding corner of forward-mapped inverse corners
        float minfx = 1e9f, minfy = 1e9f;
#pragma unroll
        for (int j = 0; j < 4; j++) {
            float fpx = x0 + (float)(j & 1);
            float fpy = y0 + (float)(j >> 1);
            float wi = ((j & 1) ? wx1 : wx0) * ((j >> 1) ? wy1 : wy0);
            if (fpx >= 0.f && fpx <= 127.f && fpy >= 0.f && fpy <= 127.f && wi > WEPS) {
                float Xp = ncoord((int)fpx), Yp = ncoord((int)fpy);
                float fgx = c_ * Xp - s_ * Yp, fgy = s_ * Xp + c_ * Yp;
                minfx = fminf(minfx, (fgx + 1.0f) * 63.5f);
                minfy = fminf(minfy, (fgy + 1.0f) * 63.5f);
            }
        }
        if (minfx < 500.f) {
            int bx = (int)floorf(minfx), by = (int)floorf(minfy);
            float cellx = (float)(bx + (lane & 3));
            float celly = (float)(by + ((lane >> 2) & 3));
            // pass 2: this lane's cell weight (recompute fwd positions)
            float wc = 0.f;
#pragma unroll
            for (int j = 0; j < 4; j++) {
                float fpx = x0 + (float)(j & 1);
                float fpy = y0 + (float)(j >> 1);
                float wi = ((j & 1) ? wx1 : wx0) * ((j >> 1) ? wy1 : wy0);
                if (fpx >= 0.f && fpx <= 127.f && fpy >= 0.f && fpy <= 127.f && wi > WEPS) {
                    int ip = (int)fpy * NW + (int)fpx;
                    float sav = g_sa[(size_t)(a * NB + b) * NHW + ip];
                    float Xp = ncoord((int)fpx), Yp = ncoord((int)fpy);
                    float fgx = c_ * Xp - s_ * Yp, fgy = s_ * Xp + c_ * Yp;
                    float tx = fmaxf(0.f, 1.0f - fabsf((fgx + 1.0f) * 63.5f - cellx));
                    float ty = fmaxf(0.f, 1.0f - fabsf((fgy + 1.0f) * 63.5f - celly));
                    wc = fmaf(wi * sav, tx * ty, wc);
                }
            }
            float t[8];
#pragma unroll
            for (int i = 0; i < 8; i++) t[i] = 0.f;
#pragma unroll
            for (int k = 0; k < 16; k++) {
                float w = __shfl_sync(0xffffffffu, wc, k);
                int cxk = bx + (k & 3), cyk = by + (k >> 2);
                if (w > WEPS && (unsigned)cxk < 128u && (unsigned)cyk < 128u) {
                    const uint4* row = (const uint4*)(g_xh +
                        ((size_t)b * NHW + cyk * NW + cxk) * NC);
                    acc_row(t, w, row[lane]);
                }
            }
            const float4* car = (const float4*)(g_ca + (size_t)(a * NB + b) * NC);
            float4 ca0 = car[lane * 2], ca1 = car[lane * 2 + 1];
            res[0] = fmaf(ca0.x, t[0], res[0]); res[1] = fmaf(ca0.y, t[1], res[1]);
            res[2] = fmaf(ca0.z, t[2], res[2]); res[3] = fmaf(ca0.w, t[3], res[3]);
            res[4] = fmaf(ca1.x, t[4], res[4]); res[5] = fmaf(ca1.y, t[5], res[5]);
            res[6] = fmaf(ca1.z, t[6], res[6]); res[7] = fmaf(ca1.w, t[7], res[7]);
        }
    }

    // smem transpose: s[pixel][channel] -> NCHW stores with /4 folded in
    *(float4*)&s[wid][lane * 8]     = make_float4(res[0], res[1], res[2], res[3]);
    *(float4*)&s[wid][lane * 8 + 4] = make_float4(res[4], res[5], res[6], res[7]);
    __syncthreads();
    int pix = lane & 15, hl = lane >> 4;
#pragma unroll
    for (int it = 0; it < 8; it++) {
        int c = wid * 16 + hl * 8 + it;
        float v = s[pix][c];
        out[((size_t)(b * NC + c)) * NHW + q0 + pix] = v * 0.25f;
    }
}

// ---------------- launch ----------------
extern "C" void kernel_launch(void* const* d_in, const int* in_sizes, int n_in,
                              void* d_out, int out_size) {
    const float* x      = (const float*)d_in[0];
    const float* angles = (const float*)d_in[1];
    const float* w1     = (const float*)d_in[2];
    const float* bng    = (const float*)d_in[3];
    const float* bnb    = (const float*)d_in[4];
    const float* bnm    = (const float*)d_in[5];
    const float* bnv    = (const float*)d_in[6];
    const float* w2     = (const float*)d_in[7];
    const float* wsp    = (const float*)d_in[8];
    float* out = (float*)d_out;

    dim3 tb(32, 32);
    k_trig<<<1, 32>>>(angles);
    k_Amap<<<(NANG * NHW) / 256, 256>>>();
    k_transpose_mean<<<dim3(NPT, NC / 64, NB), tb>>>(x);
    k_mean_reduce<<<(NANG * NB * NC) / 8, 256>>>();
    k_chatt<<<NANG * NB, 256>>>(w1, bng, bnb, bnm, bnv, w2);
    k_avgmax<<<(NANG * NB * NHW / 2) / 8, 256>>>();
    k_conv<<<(NANG * NB * NHW) / 256, 256>>>(wsp);
    k_fused<<<NB * NHW / 16, 512>>>(out);
}